// round 14
// baseline (speedup 1.0000x reference)
#include <cuda_runtime.h>
#include <cstdint>

#define NROWS 8192
#define DIN   2048
#define DOUT  2048

#define BM 128
#define BN 128
#define BK 64
#define KTILES (DIN / BK)                 // 32

// I group: cols [0,64); D group: cols [64,128)
#define N_I 64
#define N_D 64

#define STRIDE 80
#define IA_BYTES (128 * STRIDE)           // 10240
#define IB_BYTES (64 * STRIDE)            // 5120
#define ISTAGE_BYTES (IA_BYTES + IB_BYTES)// 15360
#define ISTAGES 3
#define I_SMEM (ISTAGES * ISTAGE_BYTES)   // 46080

#define DA_BYTES 8192                     // [16 kg][128 rows x 4B]
#define DB_BYTES 4096                     // [16 kg][64 cols x 4B]
#define DSTAGE_BYTES (DA_BYTES + DB_BYTES)// 12288
#define D_OFF I_SMEM
#define DYN_SMEM (I_SMEM + 2 * DSTAGE_BYTES)  // 70656

#define TILES_N (DOUT / BN)               // 16
#define NTILES_TOTAL ((NROWS / BM) * TILES_N) // 1024
#define GRID 148
#define NTHREADS 512
#define NT_TOTAL (GRID * NTHREADS)

// Device scratch (allocation-free)
__device__ uint8_t g_xq[(size_t)NROWS * DIN];   // 16 MB quantized activations
__device__ uint8_t g_wt[(size_t)DOUT * DIN];    //  4 MB W^T u8 [n][k]
__device__ unsigned g_cnt = 0;
__device__ unsigned g_epoch = 0;

// ---------------------------------------------------------------------------
__device__ __forceinline__ uint32_t smem_u32(const void* p) {
    uint32_t a;
    asm("{ .reg .u64 t; cvta.to.shared.u64 t, %1; cvt.u32.u64 %0, t; }"
        : "=r"(a) : "l"(p));
    return a;
}

__device__ __forceinline__ void cp16(uint32_t dst, const void* src) {
    asm volatile("cp.async.cg.shared.global [%0], [%1], 16;\n"
                 :: "r"(dst), "l"(src) : "memory");
}

__device__ __forceinline__ void ldsm4(uint32_t r[4], uint32_t addr) {
    asm volatile("ldmatrix.sync.aligned.m8n8.x4.shared.b16 {%0,%1,%2,%3}, [%4];"
                 : "=r"(r[0]), "=r"(r[1]), "=r"(r[2]), "=r"(r[3]) : "r"(addr));
}

__device__ __forceinline__ void mma_u8(int c[4], const uint32_t a[4],
                                       uint32_t b0, uint32_t b1) {
    asm volatile(
        "mma.sync.aligned.m16n8k32.row.col.s32.u8.u8.s32 "
        "{%0,%1,%2,%3}, {%4,%5,%6,%7}, {%8,%9}, {%0,%1,%2,%3};\n"
        : "+r"(c[0]), "+r"(c[1]), "+r"(c[2]), "+r"(c[3])
        : "r"(a[0]), "r"(a[1]), "r"(a[2]), "r"(a[3]), "r"(b0), "r"(b1));
}

__device__ __forceinline__ void barI() { asm volatile("bar.sync 1, 256;" ::: "memory"); }
__device__ __forceinline__ void barD() { asm volatile("bar.sync 2, 256;" ::: "memory"); }

// Single-use grid-wide barrier (148 CTAs, 1/SM, co-resident).
__device__ __forceinline__ void grid_barrier() {
    __syncthreads();
    if (threadIdx.x == 0) {
        unsigned e = atomicAdd(&g_epoch, 0u);
        __threadfence();
        unsigned arrived = atomicAdd(&g_cnt, 1u) + 1u;
        if (arrived == gridDim.x) {
            atomicExch(&g_cnt, 0u);
            atomicAdd(&g_epoch, 1u);
        } else {
            while (atomicAdd(&g_epoch, 0u) == e) { }
        }
        __threadfence();
    }
    __syncthreads();
}

// ---------------------------------------------------------------------------
__global__ __launch_bounds__(NTHREADS, 1) void fused_kernel(
    const float* __restrict__ x,
    const float* __restrict__ scale_p,
    const float* __restrict__ zp_p,
    const int*   __restrict__ w32,      // int32-encoded uint8 [k][n]
    const int*   __restrict__ bias,     // int32-encoded uint16 [n]
    float*       __restrict__ out)
{
    extern __shared__ uint8_t dsmem[];
    const uint32_t base = smem_u32(dsmem);

    const int tid  = threadIdx.x;
    const int gtid = blockIdx.x * NTHREADS + tid;
    const float scale = __ldg(scale_p);
    const float zp    = __ldg(zp_p);

    // ================= Phase A: quantize x + repack W^T ===================
    {
        const int total4 = (NROWS * DIN) / 4;
        for (int i = gtid; i < total4; i += NT_TOTAL) {
            float4 v = reinterpret_cast<const float4*>(x)[i];
            uint32_t q0 = (uint32_t)fminf(fmaxf(rintf(__fdiv_rn(v.x, scale)) + zp, 0.0f), 255.0f);
            uint32_t q1 = (uint32_t)fminf(fmaxf(rintf(__fdiv_rn(v.y, scale)) + zp, 0.0f), 255.0f);
            uint32_t q2 = (uint32_t)fminf(fmaxf(rintf(__fdiv_rn(v.z, scale)) + zp, 0.0f), 255.0f);
            uint32_t q3 = (uint32_t)fminf(fmaxf(rintf(__fdiv_rn(v.w, scale)) + zp, 0.0f), 255.0f);
            reinterpret_cast<uint32_t*>(g_xq)[i] = q0 | (q1 << 8) | (q2 << 16) | (q3 << 24);
        }
        const int witems = (DOUT * DIN) / 16;
        for (int it = gtid; it < witems; it += NT_TOTAL) {
            int n  = it & (DOUT - 1);
            int k0 = (it >> 11) * 16;
            uint32_t w[4];
            #pragma unroll
            for (int q = 0; q < 4; q++) {
                uint32_t p = 0;
                #pragma unroll
                for (int j = 0; j < 4; j++)
                    p |= ((uint32_t)w32[(size_t)(k0 + q * 4 + j) * DOUT + n] & 0xFFu) << (8 * j);
                w[q] = p;
            }
            uint4 v; v.x = w[0]; v.y = w[1]; v.z = w[2]; v.w = w[3];
            *reinterpret_cast<uint4*>(g_wt + (size_t)n * DIN + k0) = v;
        }
    }

    grid_barrier();

    // ================= Phase B: N-split dual GEMM =========================
    const int warp = tid >> 5;
    const int lane = tid & 31;
    const bool isI = (tid < 256);

    // ---- group I constants (8 warps: 4 m-slabs x 2 n-slabs of 32x32) ----
    const int warp_m = warp >> 1;            // 0..3 -> rows warp_m*32
    const int warp_n = warp & 1;             // 0..1 -> cols warp_n*32
    const int a_row8 = (lane & 7) + ((lane >> 3) & 1) * 8;
    const int a_koff = ((lane >> 4) & 1) * 16;
    const int b_row8 = (lane & 7) + ((lane >> 4) & 1) * 8;
    const int b_koff = ((lane >> 3) & 1) * 16;
    const int lrow = lane >> 2;
    const int lcol = lane & 3;

    // ---- group D constants (256 threads, thread tile 4 rows x 8 cols) ----
    const int td   = tid - 256;              // 0..255
    const int rgrp = td >> 3;                // 0..31 -> rows rgrp*4
    const int cgrp = td & 7;                 // 0..7  -> cols cgrp*8

    for (int tile = blockIdx.x; tile < NTILES_TOTAL; tile += GRID) {
        const int block_row = (tile >> 4) * BM;
        const int block_col = (tile & 15) * BN;

        if (isI) {
            // ===== IMMA group: cols [block_col, +64), full K ==============
            int acc[2][4][4];
            #pragma unroll
            for (int mi = 0; mi < 2; mi++)
                #pragma unroll
                for (int ni = 0; ni < 4; ni++)
                    #pragma unroll
                    for (int r = 0; r < 4; r++) acc[mi][ni][r] = 0;

            auto load_stageI = [&](int s, int t) {
                const uint32_t sa = base + s * ISTAGE_BYTES;
                const uint32_t sb = sa + IA_BYTES;
                const int kt = t * BK;
                #pragma unroll
                for (int i = 0; i < 2; i++) {          // A: 128 x 64B
                    int idx = i * 256 + tid;
                    int row = idx >> 2;
                    int c   = (idx & 3) * 16;
                    cp16(sa + row * STRIDE + c,
                         g_xq + (size_t)(block_row + row) * DIN + kt + c);
                }
                {                                       // B: 64 x 64B
                    int row = tid >> 2;
                    int c   = (tid & 3) * 16;
                    cp16(sb + row * STRIDE + c,
                         g_wt + (size_t)(block_col + row) * DIN + kt + c);
                }
                asm volatile("cp.async.commit_group;\n" ::: "memory");
            };

            load_stageI(0, 0);
            load_stageI(1, 1);

            #pragma unroll 1
            for (int t = 0; t < KTILES; t++) {
                const int s = t % ISTAGES;
                const uint32_t sa = base + s * ISTAGE_BYTES;
                const uint32_t sb = sa + IA_BYTES;

                if (t < KTILES - 1)
                    asm volatile("cp.async.wait_group 1;" ::: "memory");
                else
                    asm volatile("cp.async.wait_group 0;" ::: "memory");
                barI();

                if (t + 2 < KTILES)
                    load_stageI((t + 2) % ISTAGES, t + 2);

                #pragma unroll
                for (int kk = 0; kk < 2; kk++) {
                    const int kb = kk * 32;
                    uint32_t afr[2][4], bfr[2][4];
                    #pragma unroll
                    for (int mi = 0; mi < 2; mi++)
                        ldsm4(afr[mi], sa + (warp_m * 32 + mi * 16 + a_row8) * STRIDE
                                          + kb + a_koff);
                    #pragma unroll
                    for (int h = 0; h < 2; h++)
                        ldsm4(bfr[h], sb + (warp_n * 32 + h * 16 + b_row8) * STRIDE
                                         + kb + b_koff);
                    #pragma unroll
                    for (int mi = 0; mi < 2; mi++)
                        #pragma unroll
                        for (int ni = 0; ni < 4; ni++)
                            mma_u8(acc[mi][ni], afr[mi],
                                   bfr[ni >> 1][(ni & 1) * 2],
                                   bfr[ni >> 1][(ni & 1) * 2 + 1]);
                }
            }

            // ---- epilogue: bias, wrap, dequant, store (own columns) ----
            #pragma unroll
            for (int mi = 0; mi < 2; mi++) {
                const int rl0 = warp_m * 32 + mi * 16 + lrow;
                const int row0 = block_row + rl0;
                #pragma unroll
                for (int ni = 0; ni < 4; ni++) {
                    const int col = block_col + warp_n * 32 + ni * 8 + lcol * 2;
                    uint32_t b0 = (uint32_t)__ldg(bias + col)     & 0xFFFFu;
                    uint32_t b1 = (uint32_t)__ldg(bias + col + 1) & 0xFFFFu;
                    const int* a = acc[mi][ni];

                    uint32_t v00 = ((uint32_t)a[0] + b0) & 0xFFFFu;
                    uint32_t v01 = ((uint32_t)a[1] + b1) & 0xFFFFu;
                    uint32_t v10 = ((uint32_t)a[2] + b0) & 0xFFFFu;
                    uint32_t v11 = ((uint32_t)a[3] + b1) & 0xFFFFu;

                    float2 o0, o1;
                    o0.x = ((float)v00 - zp) * scale;
                    o0.y = ((float)v01 - zp) * scale;
                    o1.x = ((float)v10 - zp) * scale;
                    o1.y = ((float)v11 - zp) * scale;

                    *reinterpret_cast<float2*>(out + (size_t)row0 * DOUT + col) = o0;
                    *reinterpret_cast<float2*>(out + (size_t)(row0 + 8) * DOUT + col) = o1;
                }
            }
        } else {
            // ===== dp4a group: cols [block_col+64, +64), full K ===========
            const int bcolD = block_col + N_I;
            unsigned acc[4][8];
            #pragma unroll
            for (int i = 0; i < 4; i++)
                #pragma unroll
                for (int j = 0; j < 8; j++) acc[i][j] = 0u;

            uint4 va[2], vb;

            auto ldgD = [&](int dt) {
                const int kt = dt * BK;
                #pragma unroll
                for (int q = 0; q < 2; q++) {           // A: 512 chunks, 2 each
                    const int c = td * 2 + q;
                    const int r = c >> 2, c4 = c & 3;
                    va[q] = *reinterpret_cast<const uint4*>(
                        g_xq + (size_t)(block_row + r) * DIN + kt + c4 * 16);
                }
                {                                        // B: 256 chunks, 1 each
                    const int r = td >> 2, c4 = td & 3;
                    vb = *reinterpret_cast<const uint4*>(
                        g_wt + (size_t)(bcolD + r) * DIN + kt + c4 * 16);
                }
            };
            auto stsD = [&](int buf) {
                uint8_t* sA = dsmem + D_OFF + buf * DSTAGE_BYTES;
                uint8_t* sB = sA + DA_BYTES;
                #pragma unroll
                for (int q = 0; q < 2; q++) {
                    const int c = td * 2 + q;
                    const int r = c >> 2, c4 = c & 3;
                    const uint32_t wa[4] = {va[q].x, va[q].y, va[q].z, va[q].w};
                    #pragma unroll
                    for (int i = 0; i < 4; i++)
                        *reinterpret_cast<uint32_t*>(sA + (c4 * 4 + i) * 512 + r * 4) = wa[i];
                }
                {
                    const int r = td >> 2, c4 = td & 3;
                    const uint32_t wb[4] = {vb.x, vb.y, vb.z, vb.w};
                    #pragma unroll
                    for (int i = 0; i < 4; i++)
                        *reinterpret_cast<uint32_t*>(sB + (c4 * 4 + i) * 256 + r * 4) = wb[i];
                }
            };

            ldgD(0);
            stsD(0);
            barD();

            #pragma unroll 1
            for (int dt = 0; dt < KTILES; dt++) {
                const int buf = dt & 1;
                if (dt + 1 < KTILES) ldgD(dt + 1);

                const uint8_t* sA = dsmem + D_OFF + buf * DSTAGE_BYTES;
                const uint8_t* sB = sA + DA_BYTES;

                #pragma unroll 2
                for (int kg = 0; kg < 16; kg++) {
                    uint4 a4 = *reinterpret_cast<const uint4*>(
                        sA + kg * 512 + rgrp * 16);
                    uint4 b40 = *reinterpret_cast<const uint4*>(
                        sB + kg * 256 + cgrp * 32);
                    uint4 b41 = *reinterpret_cast<const uint4*>(
                        sB + kg * 256 + cgrp * 32 + 16);
                    const unsigned aw[4] = {a4.x, a4.y, a4.z, a4.w};
                    const unsigned bw[8] = {b40.x, b40.y, b40.z, b40.w,
                                            b41.x, b41.y, b41.z, b41.w};
                    #pragma unroll
                    for (int i = 0; i < 4; i++)
                        #pragma unroll
                        for (int j = 0; j < 8; j++)
                            acc[i][j] = __dp4a(aw[i], bw[j], acc[i][j]);
                }

                if (dt + 1 < KTILES) stsD(buf ^ 1);
                barD();
            }

            // ---- epilogue: bias, wrap, dequant, store (own columns) ----
            {
                const int colb = bcolD + cgrp * 8;
                uint32_t bv[8];
                #pragma unroll
                for (int j = 0; j < 8; j++)
                    bv[j] = (uint32_t)__ldg(bias + colb + j) & 0xFFFFu;

                #pragma unroll
                for (int i = 0; i < 4; i++) {
                    const int row = block_row + rgrp * 4 + i;
                    float o[8];
                    #pragma unroll
                    for (int j = 0; j < 8; j++) {
                        uint32_t v = (acc[i][j] + bv[j]) & 0xFFFFu;
                        o[j] = ((float)v - zp) * scale;
                    }
                    float4* dst = reinterpret_cast<float4*>(
                        out + (size_t)row * DOUT + colb);
                    float4 f0; f0.x = o[0]; f0.y = o[1]; f0.z = o[2]; f0.w = o[3];
                    float4 f1; f1.x = o[4]; f1.y = o[5]; f1.z = o[6]; f1.w = o[7];
                    dst[0] = f0;
                    dst[1] = f1;
                }
            }
        }
    }
}

// ---------------------------------------------------------------------------
extern "C" void kernel_launch(void* const* d_in, const int* in_sizes, int n_in,
                              void* d_out, int out_size)
{
    const float* x     = (const float*)d_in[0];
    const float* scale = (const float*)d_in[1];
    const float* zp    = (const float*)d_in[2];
    const int*   qk    = (const int*)d_in[3];
    const int*   qb    = (const int*)d_in[4];
    float* out = (float*)d_out;

    cudaFuncSetAttribute(fused_kernel,
                         cudaFuncAttributeMaxDynamicSharedMemorySize, DYN_SMEM);

    fused_kernel<<<GRID, NTHREADS, DYN_SMEM>>>(x, scale, zp, qk, qb, out);
}

// round 15
// speedup vs baseline: 1.8053x; 1.8053x over previous
#include <cuda_runtime.h>
#include <cstdint>

#define NROWS 8192
#define DIN   2048
#define DOUT  2048

#define BM 128
#define BN 128
#define BK 64

// K split between tensor (IMMA) and ALU (dp4a) warp groups
#define KTILES_I 18
#define KTILES_D 14
#define K_D_BASE (KTILES_I * BK)          // 1152

#define STRIDE 80
#define ITILE_BYTES (128 * STRIDE)        // 10240
#define ISTAGE_BYTES (2 * ITILE_BYTES)    // 20480
#define ISTAGES 3
#define I_SMEM (ISTAGES * ISTAGE_BYTES)   // 61440

#define DSTAGE_BYTES 16384                // A 8KB [kg][row] + B 8KB [kg][col]
#define DSTAGES 2
#define D_SMEM (DSTAGES * DSTAGE_BYTES)   // 32768

#define COMBW 65                          // u32 words per row (260B)
#define C_SMEM (128 * COMBW * 4)          // 33280
#define C_OFF (I_SMEM + D_SMEM)

#define DYN_SMEM (I_SMEM + D_SMEM + C_SMEM)   // 127488

#define TILES_N (DOUT / BN)               // 16
#define NTILES_TOTAL ((NROWS / BM) * TILES_N) // 1024
#define GRID 148
#define NTHREADS 512
#define NT_TOTAL (GRID * NTHREADS)

// Device scratch (allocation-free)
__device__ uint8_t g_xq[(size_t)NROWS * DIN];   // 16 MB quantized activations
__device__ uint8_t g_wt[(size_t)DOUT * DIN];    //  4 MB W^T u8 [n][k]
__device__ unsigned g_cnt = 0;
__device__ unsigned g_epoch = 0;

// ---------------------------------------------------------------------------
__device__ __forceinline__ uint32_t smem_u32(const void* p) {
    uint32_t a;
    asm("{ .reg .u64 t; cvta.to.shared.u64 t, %1; cvt.u32.u64 %0, t; }"
        : "=r"(a) : "l"(p));
    return a;
}

__device__ __forceinline__ void cp16(uint32_t dst, const void* src) {
    asm volatile("cp.async.cg.shared.global [%0], [%1], 16;\n"
                 :: "r"(dst), "l"(src) : "memory");
}

__device__ __forceinline__ void ldsm4(uint32_t r[4], uint32_t addr) {
    asm volatile("ldmatrix.sync.aligned.m8n8.x4.shared.b16 {%0,%1,%2,%3}, [%4];"
                 : "=r"(r[0]), "=r"(r[1]), "=r"(r[2]), "=r"(r[3]) : "r"(addr));
}

__device__ __forceinline__ void mma_u8(int c[4], const uint32_t a[4],
                                       uint32_t b0, uint32_t b1) {
    asm volatile(
        "mma.sync.aligned.m16n8k32.row.col.s32.u8.u8.s32 "
        "{%0,%1,%2,%3}, {%4,%5,%6,%7}, {%8,%9}, {%0,%1,%2,%3};\n"
        : "+r"(c[0]), "+r"(c[1]), "+r"(c[2]), "+r"(c[3])
        : "r"(a[0]), "r"(a[1]), "r"(a[2]), "r"(a[3]), "r"(b0), "r"(b1));
}

__device__ __forceinline__ void barI() { asm volatile("bar.sync 1, 256;" ::: "memory"); }
__device__ __forceinline__ void barD() { asm volatile("bar.sync 2, 256;" ::: "memory"); }

// Single-use grid-wide barrier (148 CTAs, 1/SM, co-resident).
__device__ __forceinline__ void grid_barrier() {
    __syncthreads();
    if (threadIdx.x == 0) {
        unsigned e = atomicAdd(&g_epoch, 0u);
        __threadfence();
        unsigned arrived = atomicAdd(&g_cnt, 1u) + 1u;
        if (arrived == gridDim.x) {
            atomicExch(&g_cnt, 0u);
            atomicAdd(&g_epoch, 1u);
        } else {
            while (atomicAdd(&g_epoch, 0u) == e) { }
        }
        __threadfence();
    }
    __syncthreads();
}

// ---------------------------------------------------------------------------
__global__ __launch_bounds__(NTHREADS, 1) void fused_kernel(
    const float* __restrict__ x,
    const float* __restrict__ scale_p,
    const float* __restrict__ zp_p,
    const int*   __restrict__ w32,      // int32-encoded uint8 [k][n]
    const int*   __restrict__ bias,     // int32-encoded uint16 [n]
    float*       __restrict__ out)
{
    extern __shared__ uint8_t dsmem[];
    const uint32_t base = smem_u32(dsmem);

    const int tid  = threadIdx.x;
    const int gtid = blockIdx.x * NTHREADS + tid;
    const float scale = __ldg(scale_p);
    const float zp    = __ldg(zp_p);

    // ================= Phase A: quantize x + repack W^T ===================
    {
        const int total4 = (NROWS * DIN) / 4;
        for (int i = gtid; i < total4; i += NT_TOTAL) {
            float4 v = reinterpret_cast<const float4*>(x)[i];
            uint32_t q0 = (uint32_t)fminf(fmaxf(rintf(__fdiv_rn(v.x, scale)) + zp, 0.0f), 255.0f);
            uint32_t q1 = (uint32_t)fminf(fmaxf(rintf(__fdiv_rn(v.y, scale)) + zp, 0.0f), 255.0f);
            uint32_t q2 = (uint32_t)fminf(fmaxf(rintf(__fdiv_rn(v.z, scale)) + zp, 0.0f), 255.0f);
            uint32_t q3 = (uint32_t)fminf(fmaxf(rintf(__fdiv_rn(v.w, scale)) + zp, 0.0f), 255.0f);
            reinterpret_cast<uint32_t*>(g_xq)[i] = q0 | (q1 << 8) | (q2 << 16) | (q3 << 24);
        }
        const int witems = (DOUT * DIN) / 16;
        for (int it = gtid; it < witems; it += NT_TOTAL) {
            int n  = it & (DOUT - 1);
            int k0 = (it >> 11) * 16;
            uint32_t w[4];
            #pragma unroll
            for (int q = 0; q < 4; q++) {
                uint32_t p = 0;
                #pragma unroll
                for (int j = 0; j < 4; j++)
                    p |= ((uint32_t)w32[(size_t)(k0 + q * 4 + j) * DOUT + n] & 0xFFu) << (8 * j);
                w[q] = p;
            }
            uint4 v; v.x = w[0]; v.y = w[1]; v.z = w[2]; v.w = w[3];
            *reinterpret_cast<uint4*>(g_wt + (size_t)n * DIN + k0) = v;
        }
    }

    grid_barrier();

    // ================= Phase B: hybrid GEMM ===============================
    const int warp = tid >> 5;
    const int lane = tid & 31;
    const bool isI = (tid < 256);

    // ---- group I constants ----
    const int warp_m = warp >> 2;
    const int warp_n = warp & 3;
    const int a_row8 = (lane & 7) + ((lane >> 3) & 1) * 8;
    const int a_koff = ((lane >> 4) & 1) * 16;
    const int b_row8 = (lane & 7) + ((lane >> 4) & 1) * 8;
    const int b_koff = ((lane >> 3) & 1) * 16;
    const int lrow = lane >> 2;
    const int lcol = lane & 3;

    // ---- group D constants ----
    const int dwarp = warp - 8;
    const int wr = dwarp >> 1;
    const int wc = dwarp & 1;
    const int rg = lane >> 2;
    const int cg = lane & 3;
    const int td = tid - 256;

    for (int tile = blockIdx.x; tile < NTILES_TOTAL; tile += GRID) {
        const int block_row = (tile >> 4) * BM;
        const int block_col = (tile & 15) * BN;

        if (isI) {
            // ================= IMMA group: k in [0, 1152) =================
            int acc[2][4][4], acc2[2][4][4];
            #pragma unroll
            for (int mi = 0; mi < 2; mi++)
                #pragma unroll
                for (int ni = 0; ni < 4; ni++)
                    #pragma unroll
                    for (int r = 0; r < 4; r++) { acc[mi][ni][r] = 0; acc2[mi][ni][r] = 0; }

            auto load_stageI = [&](int s, int t) {
                const uint32_t sa = base + s * ISTAGE_BYTES;
                const uint32_t sb = sa + ITILE_BYTES;
                const int kt = t * BK;
                #pragma unroll
                for (int i = 0; i < 2; i++) {
                    int idx = i * 256 + tid;
                    int row = idx >> 2;
                    int c   = (idx & 3) * 16;
                    cp16(sa + row * STRIDE + c,
                         g_xq + (size_t)(block_row + row) * DIN + kt + c);
                    cp16(sb + row * STRIDE + c,
                         g_wt + (size_t)(block_col + row) * DIN + kt + c);
                }
                asm volatile("cp.async.commit_group;\n" ::: "memory");
            };

            load_stageI(0, 0);
            load_stageI(1, 1);

            #pragma unroll 1
            for (int t = 0; t < KTILES_I; t++) {
                const int s = t % ISTAGES;
                const uint32_t sa = base + s * ISTAGE_BYTES;
                const uint32_t sb = sa + ITILE_BYTES;

                if (t < KTILES_I - 1)
                    asm volatile("cp.async.wait_group 1;" ::: "memory");
                else
                    asm volatile("cp.async.wait_group 0;" ::: "memory");
                barI();

                if (t + 2 < KTILES_I)
                    load_stageI((t + 2) % ISTAGES, t + 2);

                #pragma unroll
                for (int kk = 0; kk < 2; kk++) {
                    const int kb = kk * 32;
                    uint32_t afr[4][4], bfr[2][4];
                    #pragma unroll
                    for (int mi = 0; mi < 4; mi++)
                        ldsm4(afr[mi], sa + (warp_m * 64 + mi * 16 + a_row8) * STRIDE
                                          + kb + a_koff);
                    #pragma unroll
                    for (int h = 0; h < 2; h++)
                        ldsm4(bfr[h], sb + (warp_n * 32 + h * 16 + b_row8) * STRIDE
                                         + kb + b_koff);
                    #pragma unroll
                    for (int mi = 0; mi < 2; mi++)
                        #pragma unroll
                        for (int ni = 0; ni < 4; ni++) {
                            mma_u8(acc[mi][ni], afr[mi],
                                   bfr[ni >> 1][(ni & 1) * 2],
                                   bfr[ni >> 1][(ni & 1) * 2 + 1]);
                            mma_u8(acc2[mi][ni], afr[mi + 2],
                                   bfr[ni >> 1][(ni & 1) * 2],
                                   bfr[ni >> 1][(ni & 1) * 2 + 1]);
                        }
                }
            }

            __syncthreads();   // #1: dp4a partials visible

            // ---- epilogue: combine partial + bias, wrap, dequant ----
            #pragma unroll
            for (int half = 0; half < 2; half++) {
                #pragma unroll
                for (int mi = 0; mi < 2; mi++) {
                    const int mtile = half * 2 + mi;
                    const int rl0 = warp_m * 64 + mtile * 16 + lrow;
                    const int row0 = block_row + rl0;
                    #pragma unroll
                    for (int ni = 0; ni < 4; ni++) {
                        const int cl = warp_n * 32 + ni * 8 + lcol * 2;
                        const int col = block_col + cl;
                        const int* a = half ? acc2[mi][ni] : acc[mi][ni];

                        uint32_t p0 = *reinterpret_cast<const uint32_t*>(
                            dsmem + C_OFF + rl0 * (COMBW * 4) + (cl >> 1) * 4);
                        uint32_t p1 = *reinterpret_cast<const uint32_t*>(
                            dsmem + C_OFF + (rl0 + 8) * (COMBW * 4) + (cl >> 1) * 4);

                        uint32_t b0 = (uint32_t)__ldg(bias + col)     & 0xFFFFu;
                        uint32_t b1 = (uint32_t)__ldg(bias + col + 1) & 0xFFFFu;

                        uint32_t v00 = ((uint32_t)a[0] + (p0 & 0xFFFFu) + b0) & 0xFFFFu;
                        uint32_t v01 = ((uint32_t)a[1] + (p0 >> 16)     + b1) & 0xFFFFu;
                        uint32_t v10 = ((uint32_t)a[2] + (p1 & 0xFFFFu) + b0) & 0xFFFFu;
                        uint32_t v11 = ((uint32_t)a[3] + (p1 >> 16)     + b1) & 0xFFFFu;

                        float2 o0, o1;
                        o0.x = ((float)v00 - zp) * scale;
                        o0.y = ((float)v01 - zp) * scale;
                        o1.x = ((float)v10 - zp) * scale;
                        o1.y = ((float)v11 - zp) * scale;

                        *reinterpret_cast<float2*>(out + (size_t)row0 * DOUT + col) = o0;
                        *reinterpret_cast<float2*>(out + (size_t)(row0 + 8) * DOUT + col) = o1;
                    }
                }
            }

            __syncthreads();   // #2: epilogue done, D may reuse combine buffer
        } else {
            // ================= dp4a group: k in [1152, 2048) ==============
            unsigned acc[4][16];
            #pragma unroll
            for (int i = 0; i < 4; i++)
                #pragma unroll
                for (int j = 0; j < 16; j++) acc[i][j] = 0u;

            const int c0 = td * 2;
            uint4 va[2], vb[2];

            auto ldgD = [&](int dt) {
                const int kt = K_D_BASE + dt * BK;
                #pragma unroll
                for (int q = 0; q < 2; q++) {
                    const int c = c0 + q;
                    const int r = c >> 2, c4 = c & 3;
                    va[q] = *reinterpret_cast<const uint4*>(
                        g_xq + (size_t)(block_row + r) * DIN + kt + c4 * 16);
                    vb[q] = *reinterpret_cast<const uint4*>(
                        g_wt + (size_t)(block_col + r) * DIN + kt + c4 * 16);
                }
            };
            auto stsD = [&](int buf) {
                uint8_t* sA = dsmem + I_SMEM + buf * DSTAGE_BYTES;
                uint8_t* sB = sA + 8192;
                #pragma unroll
                for (int q = 0; q < 2; q++) {
                    const int c = c0 + q;
                    const int r = c >> 2, c4 = c & 3;
                    const uint32_t wa[4] = {va[q].x, va[q].y, va[q].z, va[q].w};
                    const uint32_t wb[4] = {vb[q].x, vb[q].y, vb[q].z, vb[q].w};
                    #pragma unroll
                    for (int i = 0; i < 4; i++) {
                        *reinterpret_cast<uint32_t*>(sA + (c4 * 4 + i) * 512 + r * 4) = wa[i];
                        *reinterpret_cast<uint32_t*>(sB + (c4 * 4 + i) * 512 + r * 4) = wb[i];
                    }
                }
            };

            ldgD(0);
            stsD(0);
            barD();

            #pragma unroll 1
            for (int dt = 0; dt < KTILES_D; dt++) {
                const int buf = dt & 1;
                if (dt + 1 < KTILES_D) ldgD(dt + 1);

                const uint8_t* sA = dsmem + I_SMEM + buf * DSTAGE_BYTES;
                const uint8_t* sB = sA + 8192;

                #pragma unroll 2
                for (int kg = 0; kg < 16; kg++) {
                    uint4 a4 = *reinterpret_cast<const uint4*>(
                        sA + kg * 512 + wr * 128 + rg * 16);
                    const unsigned aw[4] = {a4.x, a4.y, a4.z, a4.w};
                    #pragma unroll
                    for (int jb = 0; jb < 4; jb++) {
                        uint4 b4 = *reinterpret_cast<const uint4*>(
                            sB + kg * 512 + wc * 256 + cg * 64 + jb * 16);
                        const unsigned bw[4] = {b4.x, b4.y, b4.z, b4.w};
                        #pragma unroll
                        for (int i = 0; i < 4; i++)
                            #pragma unroll
                            for (int jj = 0; jj < 4; jj++)
                                acc[i][jb * 4 + jj] =
                                    __dp4a(aw[i], bw[jj], acc[i][jb * 4 + jj]);
                    }
                }

                if (dt + 1 < KTILES_D) stsD(buf ^ 1);
                barD();
            }

            // ---- write u16 partials to combine buffer ----
            {
                const int wbase = wc * 32 + cg * 8;
                #pragma unroll
                for (int i = 0; i < 4; i++) {
                    const int row = wr * 32 + rg * 4 + i;
                    uint32_t* dst = reinterpret_cast<uint32_t*>(
                        dsmem + C_OFF + row * (COMBW * 4));
                    #pragma unroll
                    for (int jp = 0; jp < 8; jp++) {
                        uint32_t w = (acc[i][2 * jp] & 0xFFFFu)
                                   | (acc[i][2 * jp + 1] << 16);
                        dst[wbase + jp] = w;
                    }
                }
            }

            __syncthreads();   // #1
            // group I does the epilogue
            __syncthreads();   // #2
        }
    }
}

// ---------------------------------------------------------------------------
extern "C" void kernel_launch(void* const* d_in, const int* in_sizes, int n_in,
                              void* d_out, int out_size)
{
    const float* x     = (const float*)d_in[0];
    const float* scale = (const float*)d_in[1];
    const float* zp    = (const float*)d_in[2];
    const int*   qk    = (const int*)d_in[3];
    const int*   qb    = (const int*)d_in[4];
    float* out = (float*)d_out;

    cudaFuncSetAttribute(fused_kernel,
                         cudaFuncAttributeMaxDynamicSharedMemorySize, DYN_SMEM);

    fused_kernel<<<GRID, NTHREADS, DYN_SMEM>>>(x, scale, zp, qk, qb, out);
}

// round 16
// speedup vs baseline: 1.8163x; 1.0061x over previous
#include <cuda_runtime.h>
#include <cstdint>

#define NROWS 8192
#define DIN   2048
#define DOUT  2048

#define BM 128
#define BN 128
#define BK 64

// K split between tensor (IMMA) and ALU (dp4a) warp groups
#define KTILES_I 18
#define KTILES_D 14
#define K_D_BASE (KTILES_I * BK)          // 1152

#define STRIDE 80
#define ITILE_BYTES (128 * STRIDE)        // 10240
#define ISTAGE_BYTES (2 * ITILE_BYTES)    // 20480
#define ISTAGES 3
#define I_SMEM (ISTAGES * ISTAGE_BYTES)   // 61440

#define DSTAGE_BYTES 16384                // A 8KB [kg][row] + B 8KB [kg][col]
#define DSTAGES 2
#define D_SMEM (DSTAGES * DSTAGE_BYTES)   // 32768

#define COMBW 65                          // u32 words per row (260B)
#define C_SMEM (128 * COMBW * 4)          // 33280
#define C_OFF (I_SMEM + D_SMEM)

#define DYN_SMEM (I_SMEM + D_SMEM + C_SMEM)   // 127488

#define TILES_N (DOUT / BN)               // 16
#define NTILES_TOTAL ((NROWS / BM) * TILES_N) // 1024
#define GRID 148
#define NTHREADS 512
#define NT_TOTAL (GRID * NTHREADS)

// Device scratch (allocation-free)
__device__ uint8_t g_xq[(size_t)NROWS * DIN];   // 16 MB quantized activations
__device__ uint8_t g_wt[(size_t)DOUT * DIN];    //  4 MB W^T u8 [n][k]
__device__ unsigned g_cnt = 0;
__device__ unsigned g_epoch = 0;

// ---------------------------------------------------------------------------
__device__ __forceinline__ uint32_t smem_u32(const void* p) {
    uint32_t a;
    asm("{ .reg .u64 t; cvta.to.shared.u64 t, %1; cvt.u32.u64 %0, t; }"
        : "=r"(a) : "l"(p));
    return a;
}

__device__ __forceinline__ void cp16(uint32_t dst, const void* src) {
    asm volatile("cp.async.cg.shared.global [%0], [%1], 16;\n"
                 :: "r"(dst), "l"(src) : "memory");
}

__device__ __forceinline__ void ldsm4(uint32_t r[4], uint32_t addr) {
    asm volatile("ldmatrix.sync.aligned.m8n8.x4.shared.b16 {%0,%1,%2,%3}, [%4];"
                 : "=r"(r[0]), "=r"(r[1]), "=r"(r[2]), "=r"(r[3]) : "r"(addr));
}

__device__ __forceinline__ void mma_u8(int c[4], const uint32_t a[4],
                                       uint32_t b0, uint32_t b1) {
    asm volatile(
        "mma.sync.aligned.m16n8k32.row.col.s32.u8.u8.s32 "
        "{%0,%1,%2,%3}, {%4,%5,%6,%7}, {%8,%9}, {%0,%1,%2,%3};\n"
        : "+r"(c[0]), "+r"(c[1]), "+r"(c[2]), "+r"(c[3])
        : "r"(a[0]), "r"(a[1]), "r"(a[2]), "r"(a[3]), "r"(b0), "r"(b1));
}

__device__ __forceinline__ void barI() { asm volatile("bar.sync 1, 256;" ::: "memory"); }
__device__ __forceinline__ void barD() { asm volatile("bar.sync 2, 256;" ::: "memory"); }

// Single-use grid-wide barrier (148 CTAs, 1/SM, co-resident).
__device__ __forceinline__ void grid_barrier() {
    __syncthreads();
    if (threadIdx.x == 0) {
        unsigned e = atomicAdd(&g_epoch, 0u);
        __threadfence();
        unsigned arrived = atomicAdd(&g_cnt, 1u) + 1u;
        if (arrived == gridDim.x) {
            atomicExch(&g_cnt, 0u);
            atomicAdd(&g_epoch, 1u);
        } else {
            while (atomicAdd(&g_epoch, 0u) == e) { }
        }
        __threadfence();
    }
    __syncthreads();
}

// ---------------------------------------------------------------------------
__global__ __launch_bounds__(NTHREADS, 1) void fused_kernel(
    const float* __restrict__ x,
    const float* __restrict__ scale_p,
    const float* __restrict__ zp_p,
    const int*   __restrict__ w32,      // int32-encoded uint8 [k][n]
    const int*   __restrict__ bias,     // int32-encoded uint16 [n]
    float*       __restrict__ out)
{
    extern __shared__ uint8_t dsmem[];
    const uint32_t base = smem_u32(dsmem);

    const int tid  = threadIdx.x;
    const int gtid = blockIdx.x * NTHREADS + tid;
    const float scale = __ldg(scale_p);
    const float zp    = __ldg(zp_p);

    // ================= Phase A: quantize x + repack W^T ===================
    {
        const int total4 = (NROWS * DIN) / 4;
        for (int i = gtid; i < total4; i += NT_TOTAL) {
            float4 v = reinterpret_cast<const float4*>(x)[i];
            uint32_t q0 = (uint32_t)fminf(fmaxf(rintf(__fdiv_rn(v.x, scale)) + zp, 0.0f), 255.0f);
            uint32_t q1 = (uint32_t)fminf(fmaxf(rintf(__fdiv_rn(v.y, scale)) + zp, 0.0f), 255.0f);
            uint32_t q2 = (uint32_t)fminf(fmaxf(rintf(__fdiv_rn(v.z, scale)) + zp, 0.0f), 255.0f);
            uint32_t q3 = (uint32_t)fminf(fmaxf(rintf(__fdiv_rn(v.w, scale)) + zp, 0.0f), 255.0f);
            reinterpret_cast<uint32_t*>(g_xq)[i] = q0 | (q1 << 8) | (q2 << 16) | (q3 << 24);
        }
        const int witems = (DOUT * DIN) / 16;
        for (int it = gtid; it < witems; it += NT_TOTAL) {
            int n  = it & (DOUT - 1);
            int k0 = (it >> 11) * 16;
            uint32_t w[4];
            #pragma unroll
            for (int q = 0; q < 4; q++) {
                uint32_t p = 0;
                #pragma unroll
                for (int j = 0; j < 4; j++)
                    p |= ((uint32_t)w32[(size_t)(k0 + q * 4 + j) * DOUT + n] & 0xFFu) << (8 * j);
                w[q] = p;
            }
            uint4 v; v.x = w[0]; v.y = w[1]; v.z = w[2]; v.w = w[3];
            *reinterpret_cast<uint4*>(g_wt + (size_t)n * DIN + k0) = v;
        }
    }

    grid_barrier();

    // ================= Phase B: hybrid GEMM ===============================
    const int warp = tid >> 5;
    const int lane = tid & 31;
    const bool isI = (tid < 256);

    // ---- group I constants ----
    const int warp_m = warp >> 2;
    const int warp_n = warp & 3;
    const int a_row8 = (lane & 7) + ((lane >> 3) & 1) * 8;
    const int a_koff = ((lane >> 4) & 1) * 16;
    const int b_row8 = (lane & 7) + ((lane >> 4) & 1) * 8;
    const int b_koff = ((lane >> 3) & 1) * 16;
    const int lrow = lane >> 2;
    const int lcol = lane & 3;

    // ---- group D constants ----
    const int dwarp = warp - 8;
    const int wr = dwarp >> 1;
    const int wc = dwarp & 1;
    const int rg = lane >> 2;
    const int cg = lane & 3;
    const int td = tid - 256;

    for (int tile = blockIdx.x; tile < NTILES_TOTAL; tile += GRID) {
        const int block_row = (tile >> 4) * BM;
        const int block_col = (tile & 15) * BN;

        if (isI) {
            // ================= IMMA group: k in [0, 1152) =================
            int acc[2][4][4], acc2[2][4][4];
            #pragma unroll
            for (int mi = 0; mi < 2; mi++)
                #pragma unroll
                for (int ni = 0; ni < 4; ni++)
                    #pragma unroll
                    for (int r = 0; r < 4; r++) { acc[mi][ni][r] = 0; acc2[mi][ni][r] = 0; }

            auto load_stageI = [&](int s, int t) {
                const uint32_t sa = base + s * ISTAGE_BYTES;
                const uint32_t sb = sa + ITILE_BYTES;
                const int kt = t * BK;
                #pragma unroll
                for (int i = 0; i < 2; i++) {
                    int idx = i * 256 + tid;
                    int row = idx >> 2;
                    int c   = (idx & 3) * 16;
                    cp16(sa + row * STRIDE + c,
                         g_xq + (size_t)(block_row + row) * DIN + kt + c);
                    cp16(sb + row * STRIDE + c,
                         g_wt + (size_t)(block_col + row) * DIN + kt + c);
                }
                asm volatile("cp.async.commit_group;\n" ::: "memory");
            };

            load_stageI(0, 0);
            load_stageI(1, 1);

            #pragma unroll 1
            for (int t = 0; t < KTILES_I; t++) {
                const int s = t % ISTAGES;
                const uint32_t sa = base + s * ISTAGE_BYTES;
                const uint32_t sb = sa + ITILE_BYTES;

                if (t < KTILES_I - 1)
                    asm volatile("cp.async.wait_group 1;" ::: "memory");
                else
                    asm volatile("cp.async.wait_group 0;" ::: "memory");
                barI();

                if (t + 2 < KTILES_I)
                    load_stageI((t + 2) % ISTAGES, t + 2);

                #pragma unroll
                for (int kk = 0; kk < 2; kk++) {
                    const int kb = kk * 32;
                    uint32_t afr[4][4], bfr[2][4];
                    #pragma unroll
                    for (int mi = 0; mi < 4; mi++)
                        ldsm4(afr[mi], sa + (warp_m * 64 + mi * 16 + a_row8) * STRIDE
                                          + kb + a_koff);
                    #pragma unroll
                    for (int h = 0; h < 2; h++)
                        ldsm4(bfr[h], sb + (warp_n * 32 + h * 16 + b_row8) * STRIDE
                                         + kb + b_koff);
                    #pragma unroll
                    for (int mi = 0; mi < 2; mi++)
                        #pragma unroll
                        for (int ni = 0; ni < 4; ni++) {
                            mma_u8(acc[mi][ni], afr[mi],
                                   bfr[ni >> 1][(ni & 1) * 2],
                                   bfr[ni >> 1][(ni & 1) * 2 + 1]);
                            mma_u8(acc2[mi][ni], afr[mi + 2],
                                   bfr[ni >> 1][(ni & 1) * 2],
                                   bfr[ni >> 1][(ni & 1) * 2 + 1]);
                        }
                }
            }

            __syncthreads();   // #1: dp4a partials (bias included) visible

            // ---- epilogue: combine (partial already has bias), wrap, dequant ----
            #pragma unroll
            for (int half = 0; half < 2; half++) {
                #pragma unroll
                for (int mi = 0; mi < 2; mi++) {
                    const int mtile = half * 2 + mi;
                    const int rl0 = warp_m * 64 + mtile * 16 + lrow;
                    const int row0 = block_row + rl0;
                    #pragma unroll
                    for (int ni = 0; ni < 4; ni++) {
                        const int cl = warp_n * 32 + ni * 8 + lcol * 2;
                        const int col = block_col + cl;
                        const int* a = half ? acc2[mi][ni] : acc[mi][ni];

                        uint32_t p0 = *reinterpret_cast<const uint32_t*>(
                            dsmem + C_OFF + rl0 * (COMBW * 4) + (cl >> 1) * 4);
                        uint32_t p1 = *reinterpret_cast<const uint32_t*>(
                            dsmem + C_OFF + (rl0 + 8) * (COMBW * 4) + (cl >> 1) * 4);

                        uint32_t v00 = ((uint32_t)a[0] + (p0 & 0xFFFFu)) & 0xFFFFu;
                        uint32_t v01 = ((uint32_t)a[1] + (p0 >> 16))     & 0xFFFFu;
                        uint32_t v10 = ((uint32_t)a[2] + (p1 & 0xFFFFu)) & 0xFFFFu;
                        uint32_t v11 = ((uint32_t)a[3] + (p1 >> 16))     & 0xFFFFu;

                        float2 o0, o1;
                        o0.x = ((float)v00 - zp) * scale;
                        o0.y = ((float)v01 - zp) * scale;
                        o1.x = ((float)v10 - zp) * scale;
                        o1.y = ((float)v11 - zp) * scale;

                        *reinterpret_cast<float2*>(out + (size_t)row0 * DOUT + col) = o0;
                        *reinterpret_cast<float2*>(out + (size_t)(row0 + 8) * DOUT + col) = o1;
                    }
                }
            }

            __syncthreads();   // #2: epilogue done, D may reuse combine buffer
        } else {
            // ================= dp4a group: k in [1152, 2048) ==============
            unsigned acc[4][16];
            #pragma unroll
            for (int i = 0; i < 4; i++)
                #pragma unroll
                for (int j = 0; j < 16; j++) acc[i][j] = 0u;

            const int c0 = td * 2;
            uint4 va[2], vb[2];

            auto ldgD = [&](int dt) {
                const int kt = K_D_BASE + dt * BK;
                #pragma unroll
                for (int q = 0; q < 2; q++) {
                    const int c = c0 + q;
                    const int r = c >> 2, c4 = c & 3;
                    va[q] = *reinterpret_cast<const uint4*>(
                        g_xq + (size_t)(block_row + r) * DIN + kt + c4 * 16);
                    vb[q] = *reinterpret_cast<const uint4*>(
                        g_wt + (size_t)(block_col + r) * DIN + kt + c4 * 16);
                }
            };
            auto stsD = [&](int buf) {
                uint8_t* sA = dsmem + I_SMEM + buf * DSTAGE_BYTES;
                uint8_t* sB = sA + 8192;
                #pragma unroll
                for (int q = 0; q < 2; q++) {
                    const int c = c0 + q;
                    const int r = c >> 2, c4 = c & 3;
                    const uint32_t wa[4] = {va[q].x, va[q].y, va[q].z, va[q].w};
                    const uint32_t wb[4] = {vb[q].x, vb[q].y, vb[q].z, vb[q].w};
                    #pragma unroll
                    for (int i = 0; i < 4; i++) {
                        *reinterpret_cast<uint32_t*>(sA + (c4 * 4 + i) * 512 + r * 4) = wa[i];
                        *reinterpret_cast<uint32_t*>(sB + (c4 * 4 + i) * 512 + r * 4) = wb[i];
                    }
                }
            };

            ldgD(0);
            stsD(0);
            barD();

            #pragma unroll 1
            for (int dt = 0; dt < KTILES_D; dt++) {
                const int buf = dt & 1;
                if (dt + 1 < KTILES_D) ldgD(dt + 1);

                const uint8_t* sA = dsmem + I_SMEM + buf * DSTAGE_BYTES;
                const uint8_t* sB = sA + 8192;

                #pragma unroll 2
                for (int kg = 0; kg < 16; kg++) {
                    uint4 a4 = *reinterpret_cast<const uint4*>(
                        sA + kg * 512 + wr * 128 + rg * 16);
                    const unsigned aw[4] = {a4.x, a4.y, a4.z, a4.w};
                    #pragma unroll
                    for (int jb = 0; jb < 4; jb++) {
                        uint4 b4 = *reinterpret_cast<const uint4*>(
                            sB + kg * 512 + wc * 256 + cg * 64 + jb * 16);
                        const unsigned bw[4] = {b4.x, b4.y, b4.z, b4.w};
                        #pragma unroll
                        for (int i = 0; i < 4; i++)
                            #pragma unroll
                            for (int jj = 0; jj < 4; jj++)
                                acc[i][jb * 4 + jj] =
                                    __dp4a(aw[i], bw[jj], acc[i][jb * 4 + jj]);
                    }
                }

                if (dt + 1 < KTILES_D) stsD(buf ^ 1);
                barD();
            }

            // ---- fold bias into partials, write u16 to combine buffer ----
            {
                const int colb = block_col + wc * 64 + cg * 16;
                uint32_t bv[16];
                #pragma unroll
                for (int j = 0; j < 16; j++)
                    bv[j] = (uint32_t)__ldg(bias + colb + j) & 0xFFFFu;

                const int wbase = wc * 32 + cg * 8;
                #pragma unroll
                for (int i = 0; i < 4; i++) {
                    const int row = wr * 32 + rg * 4 + i;
                    uint32_t* dst = reinterpret_cast<uint32_t*>(
                        dsmem + C_OFF + row * (COMBW * 4));
                    #pragma unroll
                    for (int jp = 0; jp < 8; jp++) {
                        uint32_t w = ((acc[i][2 * jp]     + bv[2 * jp])     & 0xFFFFu)
                                   | ((acc[i][2 * jp + 1] + bv[2 * jp + 1]) << 16);
                        dst[wbase + jp] = w;
                    }
                }
            }

            __syncthreads();   // #1
            // group I does the epilogue
            __syncthreads();   // #2
        }
    }
}

// ---------------------------------------------------------------------------
extern "C" void kernel_launch(void* const* d_in, const int* in_sizes, int n_in,
                              void* d_out, int out_size)
{
    const float* x     = (const float*)d_in[0];
    const float* scale = (const float*)d_in[1];
    const float* zp    = (const float*)d_in[2];
    const int*   qk    = (const int*)d_in[3];
    const int*   qb    = (const int*)d_in[4];
    float* out = (float*)d_out;

    cudaFuncSetAttribute(fused_kernel,
                         cudaFuncAttributeMaxDynamicSharedMemorySize, DYN_SMEM);

    fused_kernel<<<GRID, NTHREADS, DYN_SMEM>>>(x, scale, zp, qk, qb, out);
}

// round 17
// speedup vs baseline: 1.8244x; 1.0045x over previous
#include <cuda_runtime.h>
#include <cstdint>

#define NROWS 8192
#define DIN   2048
#define DOUT  2048

#define BM 128
#define BN 128
#define BK 64

// K split between tensor (IMMA) and ALU (dp4a) warp groups
#define KTILES_I 18
#define KTILES_D 14
#define K_D_BASE (KTILES_I * BK)          // 1152

#define STRIDE 80
#define ITILE_BYTES (128 * STRIDE)        // 10240
#define ISTAGE_BYTES (2 * ITILE_BYTES)    // 20480
#define ISTAGES 3
#define I_SMEM (ISTAGES * ISTAGE_BYTES)   // 61440

#define DSTAGE_BYTES 16384                // A 8KB [kg][row] + B 8KB [kg][col]
#define DSTAGES 2
#define D_SMEM (DSTAGES * DSTAGE_BYTES)   // 32768

#define COMBW 68                          // u32 words per row (272B): 68*rl0 ≡ 4*lrow (mod 32)
                                          // -> epilogue partial reads are bank-conflict-free
#define C_SMEM (128 * COMBW * 4)          // 34816
#define C_OFF (I_SMEM + D_SMEM)

#define DYN_SMEM (I_SMEM + D_SMEM + C_SMEM)   // 129024

#define TILES_N (DOUT / BN)               // 16
#define NTILES_TOTAL ((NROWS / BM) * TILES_N) // 1024
#define GRID 148
#define NTHREADS 512
#define NT_TOTAL (GRID * NTHREADS)

// Device scratch (allocation-free)
__device__ uint8_t g_xq[(size_t)NROWS * DIN];   // 16 MB quantized activations
__device__ uint8_t g_wt[(size_t)DOUT * DIN];    //  4 MB W^T u8 [n][k]
__device__ unsigned g_cnt = 0;
__device__ unsigned g_epoch = 0;

// ---------------------------------------------------------------------------
__device__ __forceinline__ uint32_t smem_u32(const void* p) {
    uint32_t a;
    asm("{ .reg .u64 t; cvta.to.shared.u64 t, %1; cvt.u32.u64 %0, t; }"
        : "=r"(a) : "l"(p));
    return a;
}

__device__ __forceinline__ void cp16(uint32_t dst, const void* src) {
    asm volatile("cp.async.cg.shared.global [%0], [%1], 16;\n"
                 :: "r"(dst), "l"(src) : "memory");
}

__device__ __forceinline__ void ldsm4(uint32_t r[4], uint32_t addr) {
    asm volatile("ldmatrix.sync.aligned.m8n8.x4.shared.b16 {%0,%1,%2,%3}, [%4];"
                 : "=r"(r[0]), "=r"(r[1]), "=r"(r[2]), "=r"(r[3]) : "r"(addr));
}

__device__ __forceinline__ void mma_u8(int c[4], const uint32_t a[4],
                                       uint32_t b0, uint32_t b1) {
    asm volatile(
        "mma.sync.aligned.m16n8k32.row.col.s32.u8.u8.s32 "
        "{%0,%1,%2,%3}, {%4,%5,%6,%7}, {%8,%9}, {%0,%1,%2,%3};\n"
        : "+r"(c[0]), "+r"(c[1]), "+r"(c[2]), "+r"(c[3])
        : "r"(a[0]), "r"(a[1]), "r"(a[2]), "r"(a[3]), "r"(b0), "r"(b1));
}

__device__ __forceinline__ void barI() { asm volatile("bar.sync 1, 256;" ::: "memory"); }
__device__ __forceinline__ void barD() { asm volatile("bar.sync 2, 256;" ::: "memory"); }

// Single-use grid-wide barrier (148 CTAs, 1/SM, co-resident).
__device__ __forceinline__ void grid_barrier() {
    __syncthreads();
    if (threadIdx.x == 0) {
        unsigned e = atomicAdd(&g_epoch, 0u);
        __threadfence();
        unsigned arrived = atomicAdd(&g_cnt, 1u) + 1u;
        if (arrived == gridDim.x) {
            atomicExch(&g_cnt, 0u);
            atomicAdd(&g_epoch, 1u);
        } else {
            while (atomicAdd(&g_epoch, 0u) == e) { }
        }
        __threadfence();
    }
    __syncthreads();
}

// ---------------------------------------------------------------------------
__global__ __launch_bounds__(NTHREADS, 1) void fused_kernel(
    const float* __restrict__ x,
    const float* __restrict__ scale_p,
    const float* __restrict__ zp_p,
    const int*   __restrict__ w32,      // int32-encoded uint8 [k][n]
    const int*   __restrict__ bias,     // int32-encoded uint16 [n]
    float*       __restrict__ out)
{
    extern __shared__ uint8_t dsmem[];
    const uint32_t base = smem_u32(dsmem);

    const int tid  = threadIdx.x;
    const int gtid = blockIdx.x * NTHREADS + tid;
    const float scale = __ldg(scale_p);
    const float zp    = __ldg(zp_p);

    // ================= Phase A: quantize x + repack W^T ===================
    {
        const int total4 = (NROWS * DIN) / 4;
        for (int i = gtid; i < total4; i += NT_TOTAL) {
            float4 v = reinterpret_cast<const float4*>(x)[i];
            uint32_t q0 = (uint32_t)fminf(fmaxf(rintf(__fdiv_rn(v.x, scale)) + zp, 0.0f), 255.0f);
            uint32_t q1 = (uint32_t)fminf(fmaxf(rintf(__fdiv_rn(v.y, scale)) + zp, 0.0f), 255.0f);
            uint32_t q2 = (uint32_t)fminf(fmaxf(rintf(__fdiv_rn(v.z, scale)) + zp, 0.0f), 255.0f);
            uint32_t q3 = (uint32_t)fminf(fmaxf(rintf(__fdiv_rn(v.w, scale)) + zp, 0.0f), 255.0f);
            reinterpret_cast<uint32_t*>(g_xq)[i] = q0 | (q1 << 8) | (q2 << 16) | (q3 << 24);
        }
        const int witems = (DOUT * DIN) / 16;
        for (int it = gtid; it < witems; it += NT_TOTAL) {
            int n  = it & (DOUT - 1);
            int k0 = (it >> 11) * 16;
            uint32_t w[4];
            #pragma unroll
            for (int q = 0; q < 4; q++) {
                uint32_t p = 0;
                #pragma unroll
                for (int j = 0; j < 4; j++)
                    p |= ((uint32_t)w32[(size_t)(k0 + q * 4 + j) * DOUT + n] & 0xFFu) << (8 * j);
                w[q] = p;
            }
            uint4 v; v.x = w[0]; v.y = w[1]; v.z = w[2]; v.w = w[3];
            *reinterpret_cast<uint4*>(g_wt + (size_t)n * DIN + k0) = v;
        }
    }

    grid_barrier();

    // ================= Phase B: hybrid GEMM ===============================
    const int warp = tid >> 5;
    const int lane = tid & 31;
    const bool isI = (tid < 256);

    // ---- group I constants ----
    const int warp_m = warp >> 2;
    const int warp_n = warp & 3;
    const int a_row8 = (lane & 7) + ((lane >> 3) & 1) * 8;
    const int a_koff = ((lane >> 4) & 1) * 16;
    const int b_row8 = (lane & 7) + ((lane >> 4) & 1) * 8;
    const int b_koff = ((lane >> 3) & 1) * 16;
    const int lrow = lane >> 2;
    const int lcol = lane & 3;

    // ---- group D constants ----
    const int dwarp = warp - 8;
    const int wr = dwarp >> 1;
    const int wc = dwarp & 1;
    const int rg = lane >> 2;
    const int cg = lane & 3;
    const int td = tid - 256;

    for (int tile = blockIdx.x; tile < NTILES_TOTAL; tile += GRID) {
        const int block_row = (tile >> 4) * BM;
        const int block_col = (tile & 15) * BN;

        if (isI) {
            // ================= IMMA group: k in [0, 1152) =================
            int acc[2][4][4], acc2[2][4][4];
            #pragma unroll
            for (int mi = 0; mi < 2; mi++)
                #pragma unroll
                for (int ni = 0; ni < 4; ni++)
                    #pragma unroll
                    for (int r = 0; r < 4; r++) { acc[mi][ni][r] = 0; acc2[mi][ni][r] = 0; }

            auto load_stageI = [&](int s, int t) {
                const uint32_t sa = base + s * ISTAGE_BYTES;
                const uint32_t sb = sa + ITILE_BYTES;
                const int kt = t * BK;
                #pragma unroll
                for (int i = 0; i < 2; i++) {
                    int idx = i * 256 + tid;
                    int row = idx >> 2;
                    int c   = (idx & 3) * 16;
                    cp16(sa + row * STRIDE + c,
                         g_xq + (size_t)(block_row + row) * DIN + kt + c);
                    cp16(sb + row * STRIDE + c,
                         g_wt + (size_t)(block_col + row) * DIN + kt + c);
                }
                asm volatile("cp.async.commit_group;\n" ::: "memory");
            };

            load_stageI(0, 0);
            load_stageI(1, 1);

            #pragma unroll 1
            for (int t = 0; t < KTILES_I; t++) {
                const int s = t % ISTAGES;
                const uint32_t sa = base + s * ISTAGE_BYTES;
                const uint32_t sb = sa + ITILE_BYTES;

                if (t < KTILES_I - 1)
                    asm volatile("cp.async.wait_group 1;" ::: "memory");
                else
                    asm volatile("cp.async.wait_group 0;" ::: "memory");
                barI();

                if (t + 2 < KTILES_I)
                    load_stageI((t + 2) % ISTAGES, t + 2);

                #pragma unroll
                for (int kk = 0; kk < 2; kk++) {
                    const int kb = kk * 32;
                    uint32_t afr[4][4], bfr[2][4];
                    #pragma unroll
                    for (int mi = 0; mi < 4; mi++)
                        ldsm4(afr[mi], sa + (warp_m * 64 + mi * 16 + a_row8) * STRIDE
                                          + kb + a_koff);
                    #pragma unroll
                    for (int h = 0; h < 2; h++)
                        ldsm4(bfr[h], sb + (warp_n * 32 + h * 16 + b_row8) * STRIDE
                                         + kb + b_koff);
                    #pragma unroll
                    for (int mi = 0; mi < 2; mi++)
                        #pragma unroll
                        for (int ni = 0; ni < 4; ni++) {
                            mma_u8(acc[mi][ni], afr[mi],
                                   bfr[ni >> 1][(ni & 1) * 2],
                                   bfr[ni >> 1][(ni & 1) * 2 + 1]);
                            mma_u8(acc2[mi][ni], afr[mi + 2],
                                   bfr[ni >> 1][(ni & 1) * 2],
                                   bfr[ni >> 1][(ni & 1) * 2 + 1]);
                        }
                }
            }

            __syncthreads();   // #1: dp4a partials (bias included) visible

            // ---- epilogue: combine (partial already has bias), wrap, dequant ----
            #pragma unroll
            for (int half = 0; half < 2; half++) {
                #pragma unroll
                for (int mi = 0; mi < 2; mi++) {
                    const int mtile = half * 2 + mi;
                    const int rl0 = warp_m * 64 + mtile * 16 + lrow;
                    const int row0 = block_row + rl0;
                    #pragma unroll
                    for (int ni = 0; ni < 4; ni++) {
                        const int cl = warp_n * 32 + ni * 8 + lcol * 2;
                        const int col = block_col + cl;
                        const int* a = half ? acc2[mi][ni] : acc[mi][ni];

                        uint32_t p0 = *reinterpret_cast<const uint32_t*>(
                            dsmem + C_OFF + rl0 * (COMBW * 4) + (cl >> 1) * 4);
                        uint32_t p1 = *reinterpret_cast<const uint32_t*>(
                            dsmem + C_OFF + (rl0 + 8) * (COMBW * 4) + (cl >> 1) * 4);

                        uint32_t v00 = ((uint32_t)a[0] + (p0 & 0xFFFFu)) & 0xFFFFu;
                        uint32_t v01 = ((uint32_t)a[1] + (p0 >> 16))     & 0xFFFFu;
                        uint32_t v10 = ((uint32_t)a[2] + (p1 & 0xFFFFu)) & 0xFFFFu;
                        uint32_t v11 = ((uint32_t)a[3] + (p1 >> 16))     & 0xFFFFu;

                        float2 o0, o1;
                        o0.x = ((float)v00 - zp) * scale;
                        o0.y = ((float)v01 - zp) * scale;
                        o1.x = ((float)v10 - zp) * scale;
                        o1.y = ((float)v11 - zp) * scale;

                        *reinterpret_cast<float2*>(out + (size_t)row0 * DOUT + col) = o0;
                        *reinterpret_cast<float2*>(out + (size_t)(row0 + 8) * DOUT + col) = o1;
                    }
                }
            }

            __syncthreads();   // #2: epilogue done, D may reuse combine buffer
        } else {
            // ================= dp4a group: k in [1152, 2048) ==============
            unsigned acc[4][16];
            #pragma unroll
            for (int i = 0; i < 4; i++)
                #pragma unroll
                for (int j = 0; j < 16; j++) acc[i][j] = 0u;

            const int c0 = td * 2;
            uint4 va[2], vb[2];

            auto ldgD = [&](int dt) {
                const int kt = K_D_BASE + dt * BK;
                #pragma unroll
                for (int q = 0; q < 2; q++) {
                    const int c = c0 + q;
                    const int r = c >> 2, c4 = c & 3;
                    va[q] = *reinterpret_cast<const uint4*>(
                        g_xq + (size_t)(block_row + r) * DIN + kt + c4 * 16);
                    vb[q] = *reinterpret_cast<const uint4*>(
                        g_wt + (size_t)(block_col + r) * DIN + kt + c4 * 16);
                }
            };
            auto stsD = [&](int buf) {
                uint8_t* sA = dsmem + I_SMEM + buf * DSTAGE_BYTES;
                uint8_t* sB = sA + 8192;
                #pragma unroll
                for (int q = 0; q < 2; q++) {
                    const int c = c0 + q;
                    const int r = c >> 2, c4 = c & 3;
                    const uint32_t wa[4] = {va[q].x, va[q].y, va[q].z, va[q].w};
                    const uint32_t wb[4] = {vb[q].x, vb[q].y, vb[q].z, vb[q].w};
                    #pragma unroll
                    for (int i = 0; i < 4; i++) {
                        *reinterpret_cast<uint32_t*>(sA + (c4 * 4 + i) * 512 + r * 4) = wa[i];
                        *reinterpret_cast<uint32_t*>(sB + (c4 * 4 + i) * 512 + r * 4) = wb[i];
                    }
                }
            };

            ldgD(0);
            stsD(0);
            barD();

            #pragma unroll 1
            for (int dt = 0; dt < KTILES_D; dt++) {
                const int buf = dt & 1;
                if (dt + 1 < KTILES_D) ldgD(dt + 1);

                const uint8_t* sA = dsmem + I_SMEM + buf * DSTAGE_BYTES;
                const uint8_t* sB = sA + 8192;

                #pragma unroll 2
                for (int kg = 0; kg < 16; kg++) {
                    uint4 a4 = *reinterpret_cast<const uint4*>(
                        sA + kg * 512 + wr * 128 + rg * 16);
                    const unsigned aw[4] = {a4.x, a4.y, a4.z, a4.w};
                    #pragma unroll
                    for (int jb = 0; jb < 4; jb++) {
                        uint4 b4 = *reinterpret_cast<const uint4*>(
                            sB + kg * 512 + wc * 256 + cg * 64 + jb * 16);
                        const unsigned bw[4] = {b4.x, b4.y, b4.z, b4.w};
                        #pragma unroll
                        for (int i = 0; i < 4; i++)
                            #pragma unroll
                            for (int jj = 0; jj < 4; jj++)
                                acc[i][jb * 4 + jj] =
                                    __dp4a(aw[i], bw[jj], acc[i][jb * 4 + jj]);
                    }
                }

                if (dt + 1 < KTILES_D) stsD(buf ^ 1);
                barD();
            }

            // ---- fold bias into partials, write u16 to combine buffer ----
            {
                const int colb = block_col + wc * 64 + cg * 16;
                uint32_t bv[16];
                #pragma unroll
                for (int j = 0; j < 16; j++)
                    bv[j] = (uint32_t)__ldg(bias + colb + j) & 0xFFFFu;

                const int wbase = wc * 32 + cg * 8;
                #pragma unroll
                for (int i = 0; i < 4; i++) {
                    const int row = wr * 32 + rg * 4 + i;
                    uint32_t* dst = reinterpret_cast<uint32_t*>(
                        dsmem + C_OFF + row * (COMBW * 4));
                    #pragma unroll
                    for (int jp = 0; jp < 8; jp++) {
                        uint32_t w = ((acc[i][2 * jp]     + bv[2 * jp])     & 0xFFFFu)
                                   | ((acc[i][2 * jp + 1] + bv[2 * jp + 1]) << 16);
                        dst[wbase + jp] = w;
                    }
                }
            }

            __syncthreads();   // #1
            // group I does the epilogue
            __syncthreads();   // #2
        }
    }
}

// ---------------------------------------------------------------------------
extern "C" void kernel_launch(void* const* d_in, const int* in_sizes, int n_in,
                              void* d_out, int out_size)
{
    const float* x     = (const float*)d_in[0];
    const float* scale = (const float*)d_in[1];
    const float* zp    = (const float*)d_in[2];
    const int*   qk    = (const int*)d_in[3];
    const int*   qb    = (const int*)d_in[4];
    float* out = (float*)d_out;

    cudaFuncSetAttribute(fused_kernel,
                         cudaFuncAttributeMaxDynamicSharedMemorySize, DYN_SMEM);

    fused_kernel<<<GRID, NTHREADS, DYN_SMEM>>>(x, scale, zp, qk, qb, out);
}